// round 4
// baseline (speedup 1.0000x reference)
#include <cuda_runtime.h>
#include <cstdint>

#define N_ATOMS 50000
#define M_NBR   12
#define N_ROWS  (N_ATOMS * M_NBR)
#define BN_EPS  1e-5f

// ---------------- scratch (device globals; no allocation) ----------------
__device__ float  g_P[(size_t)N_ATOMS * 512];       // [i][0:256)=atom@W1+bias, [256:512)=atom@W2
__device__ float  g_gated[(size_t)N_ROWS * 256];    // pre-BN gated features (active rows only)
__device__ float  g_nbrsum[(size_t)N_ATOMS * 128];
__device__ float  g_stats1[513];                    // S[256], SS[256], cnt
__device__ float  g_stats2[256];                    // S2[128], SS2[128]
__device__ int    g_rows[N_ROWS];                   // compacted active row indices
__device__ int    g_nactive;
__device__ float2 g_W3dup[64 * 256];                // W3 prepacked as (w,w) pairs, 128KB

// ---------------- f32x2 helpers ----------------
__device__ __forceinline__ void fma2(uint64_t& d, uint64_t a, uint64_t b) {
    asm("fma.rn.f32x2 %0, %1, %2, %0;" : "+l"(d) : "l"(a), "l"(b));
}
__device__ __forceinline__ float lo32(uint64_t v) { return __uint_as_float((unsigned)(v & 0xffffffffu)); }
__device__ __forceinline__ float hi32(uint64_t v) { return __uint_as_float((unsigned)(v >> 32)); }

__device__ __forceinline__ float sigmoid_fast(float x) {
    float z = __expf(-fabsf(x));
    return __fdividef((x >= 0.f) ? 1.f : z, 1.f + z);
}
__device__ __forceinline__ float softplus_fast(float x) {
    return fmaxf(x, 0.f) + __logf(1.f + __expf(-fabsf(x)));
}

// ---------------- kernel 0: zero stats ----------------
__global__ void zero_stats_kernel() {
    int t = threadIdx.x;
    if (t < 513) g_stats1[t] = 0.f;
    if (t < 256) g_stats2[t] = 0.f;
    if (t == 0)  g_nactive = 0;
}

// ---------------- prepack W3 as (w,w) float2 ----------------
__global__ void prepack_kernel(const float* __restrict__ W) {
    int t = blockIdx.x * 256 + threadIdx.x;      // 0 .. 16383
    if (t < 64 * 256) {
        float w = W[256 * 256 + t];
        g_W3dup[t] = make_float2(w, w);
    }
}

// ---------------- kernel C: compact active rows ----------------
__global__ void compact_kernel(const float* __restrict__ mask) {
    int t = blockIdx.x * 256 + threadIdx.x;
    bool in = (t < N_ROWS) && (mask[t] != 0.f);
    unsigned b = __ballot_sync(0xffffffffu, in);
    int lane = threadIdx.x & 31;
    int cnt = __popc(b);
    int base = 0;
    if (lane == 0 && cnt) {
        base = atomicAdd(&g_nactive, cnt);
        atomicAdd(&g_stats1[512], (float)cnt);
    }
    base = __shfl_sync(0xffffffffu, base, 0);
    if (in) g_rows[base + __popc(b & ((1u << lane) - 1u))] = t;
}

// ---------------- kernel A: P = atom @ [W1|W2] + bias-fold ----
// Grid (1563, 2): 32 rows x 256 cols per block (blockIdx.y = which half of W).
// Thread rg=tid>>5 owns rows rg*4..rg*4+3 (2 f32x2 pairs), cols cx+32q (q=0..7).
// Inner k: 1 broadcast LDS.128 (A pairs) + 8 LDS.64 (prepacked (w,w)) + 16 fma2.
__global__ void __launch_bounds__(256, 3) gemmA_kernel(
    const float* __restrict__ atom, const float* __restrict__ W,
    const float* __restrict__ bias)
{
    __shared__ float  s_a[128 * 32];      // [k][r], 16KB
    __shared__ float2 s_w2[16 * 256];     // chunk [kk][c] duplicated pairs, 32KB

    const int tid  = threadIdx.x;
    const int row0 = blockIdx.x * 32;
    const int h    = blockIdx.y;          // 0 -> W1 (cols 0..255 of P), 1 -> W2 (cols 256..511)

    for (int t = tid; t < 1024; t += 256) {     // 32 rows x 32 float4
        int r  = t & 31;
        int kq = t >> 5;
        float4 v = make_float4(0.f, 0.f, 0.f, 0.f);
        int gr = row0 + r;
        if (gr < N_ATOMS) v = *(const float4*)(atom + (size_t)gr * 128 + kq * 4);
        s_a[(kq * 4 + 0) * 32 + r] = v.x;
        s_a[(kq * 4 + 1) * 32 + r] = v.y;
        s_a[(kq * 4 + 2) * 32 + r] = v.z;
        s_a[(kq * 4 + 3) * 32 + r] = v.w;
    }

    const int rg = tid >> 5;              // 0..7 -> rows rg*4 .. rg*4+3
    const int cx = tid & 31;              // cols cx + 32q

    uint64_t acc[2][8];
    #pragma unroll
    for (int p = 0; p < 2; p++)
        #pragma unroll
        for (int q = 0; q < 8; q++) acc[p][q] = 0ull;

    for (int chunk = 0; chunk < 8; chunk++) {
        const int k0 = chunk * 16;
        __syncthreads();
        // stage W chunk duplicated: 16 k x 256 c
        for (int t = tid; t < 1024; t += 256) {
            int kk = t >> 6;
            int c4 = (t & 63) * 4;
            float4 v = *(const float4*)(W + (size_t)(h * 128 + k0 + kk) * 256 + c4);
            s_w2[kk * 256 + c4 + 0] = make_float2(v.x, v.x);
            s_w2[kk * 256 + c4 + 1] = make_float2(v.y, v.y);
            s_w2[kk * 256 + c4 + 2] = make_float2(v.z, v.z);
            s_w2[kk * 256 + c4 + 3] = make_float2(v.w, v.w);
        }
        __syncthreads();

        #pragma unroll 4
        for (int kk = 0; kk < 16; kk++) {
            ulonglong2 a2 = *(const ulonglong2*)(s_a + (k0 + kk) * 32 + rg * 4);  // broadcast
            const uint64_t* swp = (const uint64_t*)(s_w2 + kk * 256 + cx);
            uint64_t wp[8];
            #pragma unroll
            for (int q = 0; q < 8; q++) wp[q] = swp[32 * q];
            #pragma unroll
            for (int q = 0; q < 8; q++) {
                fma2(acc[0][q], a2.x, wp[q]);
                fma2(acc[1][q], a2.y, wp[q]);
            }
        }
    }

    #pragma unroll
    for (int p = 0; p < 2; p++) {
        int r_lo = row0 + rg * 4 + 2 * p;
        int r_hi = r_lo + 1;
        #pragma unroll
        for (int q = 0; q < 8; q++) {
            int cloc = cx + 32 * q;
            float badd = (h == 0) ? bias[cloc] : 0.f;
            size_t col = (size_t)h * 256 + cloc;
            if (r_lo < N_ATOMS) g_P[(size_t)r_lo * 512 + col] = lo32(acc[p][q]) + badd;
            if (r_hi < N_ATOMS) g_P[(size_t)r_hi * 512 + col] = hi32(acc[p][q]) + badd;
        }
    }
}

// ---------------- kernel B: gated = nbr@W3 + P1(+b) + P2[idx] (active rows) ----
// 32 compacted rows x 256 cols per block. Thread: 2 row-pairs x 8 cols.
__global__ void __launch_bounds__(256, 3) kernelB(
    const float* __restrict__ nbr, const int* __restrict__ idx)
{
    __shared__ float  s_v[64 * 32];       // [k][r], 8KB
    __shared__ float2 s_w2[16 * 256];     // W3 chunk duplicated, 32KB
    __shared__ int    s_row[32];
    __shared__ int    s_atom[32];
    __shared__ int    s_idx[32];
    __shared__ float  s_st[512];          // per-col partial stats

    const int na    = g_nactive;
    const int slot0 = blockIdx.x * 32;
    if (slot0 >= na) return;

    const int tid = threadIdx.x;

    if (tid < 32) {
        int slot = slot0 + tid;
        int gr = (slot < na) ? g_rows[slot] : -1;
        s_row[tid]  = gr;
        s_atom[tid] = (gr >= 0) ? (gr / 12) : 0;
        s_idx[tid]  = (gr >= 0) ? idx[gr] : 0;
    }
    s_st[tid] = 0.f;
    s_st[tid + 256] = 0.f;
    __syncthreads();

    for (int t = tid; t < 512; t += 256) {       // 32 rows x 16 float4
        int r  = t & 31;
        int kq = t >> 5;
        int gr = s_row[r];
        float4 v = make_float4(0.f, 0.f, 0.f, 0.f);
        if (gr >= 0) v = *(const float4*)(nbr + (size_t)gr * 64 + kq * 4);
        s_v[(kq * 4 + 0) * 32 + r] = v.x;
        s_v[(kq * 4 + 1) * 32 + r] = v.y;
        s_v[(kq * 4 + 2) * 32 + r] = v.z;
        s_v[(kq * 4 + 3) * 32 + r] = v.w;
    }

    const int rg = tid >> 5;              // rows rg*4 .. rg*4+3
    const int cx = tid & 31;              // cols cx + 32q

    uint64_t acc[2][8];
    #pragma unroll
    for (int p = 0; p < 2; p++)
        #pragma unroll
        for (int q = 0; q < 8; q++) acc[p][q] = 0ull;

    for (int chunk = 0; chunk < 4; chunk++) {
        const int k0 = chunk * 16;
        __syncthreads();
        for (int t = tid; t < 2048; t += 256) {      // 16k x 256c float2, as float4 copies
            int kk = t >> 7;
            int e  = (t & 127) * 2;
            *(float4*)(s_w2 + kk * 256 + e) =
                *(const float4*)(g_W3dup + (size_t)(k0 + kk) * 256 + e);
        }
        __syncthreads();

        #pragma unroll 4
        for (int kk = 0; kk < 16; kk++) {
            ulonglong2 a2 = *(const ulonglong2*)(s_v + (k0 + kk) * 32 + rg * 4);  // broadcast
            const uint64_t* swp = (const uint64_t*)(s_w2 + kk * 256 + cx);
            uint64_t wp[8];
            #pragma unroll
            for (int q = 0; q < 8; q++) wp[q] = swp[32 * q];
            #pragma unroll
            for (int q = 0; q < 8; q++) {
                fma2(acc[0][q], a2.x, wp[q]);
                fma2(acc[1][q], a2.y, wp[q]);
            }
        }
    }

    // epilogue: add P1(+bias) + P2[idx], store gated, accumulate per-col stats
    float sq[8], ssq[8];
    #pragma unroll
    for (int q = 0; q < 8; q++) { sq[q] = 0.f; ssq[q] = 0.f; }

    #pragma unroll
    for (int rr4 = 0; rr4 < 4; rr4++) {           // 4 rows of this thread
        int rr   = rg * 4 + rr4;
        int slot = slot0 + rr;
        if (slot >= na) continue;
        int gr = s_row[rr];
        const float* P1 = g_P + (size_t)s_atom[rr] * 512;
        const float* P2 = g_P + (size_t)s_idx[rr] * 512 + 256;
        float* Gout = g_gated + (size_t)gr * 256;
        uint64_t* arow = acc[rr4 >> 1];
        bool hi = (rr4 & 1);
        #pragma unroll
        for (int q = 0; q < 8; q++) {
            int c = cx + 32 * q;
            float y = hi ? hi32(arow[q]) : lo32(arow[q]);
            float g = y + P1[c] + P2[c];
            Gout[c] = g;
            sq[q]  += g;
            ssq[q]  = fmaf(g, g, ssq[q]);
        }
    }
    #pragma unroll
    for (int q = 0; q < 8; q++) {
        int c = cx + 32 * q;
        atomicAdd(&s_st[c],       sq[q]);
        atomicAdd(&s_st[256 + c], ssq[q]);
    }
    __syncthreads();
    atomicAdd(&g_stats1[tid],       s_st[tid]);
    atomicAdd(&g_stats1[256 + tid], s_st[256 + tid]);
}

// ---------------- kernel D: BN1 + sigmoid*softplus + sum_j, + BN2 stats ----
__global__ void __launch_bounds__(128) kernelD(
    const float* __restrict__ mask,
    const float* __restrict__ gamma1, const float* __restrict__ beta1)
{
    const int c     = threadIdx.x;
    const int atom0 = blockIdx.x * 8;

    const float inv_cnt = __fdividef(1.f, g_stats1[512]);
    const float mf = g_stats1[c]       * inv_cnt;
    const float mc = g_stats1[c + 128] * inv_cnt;
    const float vf = g_stats1[256 + c]       * inv_cnt - mf * mf;
    const float vc = g_stats1[256 + c + 128] * inv_cnt - mc * mc;
    const float sf = rsqrtf(vf + BN_EPS) * gamma1[c];
    const float sc = rsqrtf(vc + BN_EPS) * gamma1[c + 128];
    const float bf = beta1[c];
    const float bcr = beta1[c + 128];

    float sloc = 0.f, ssloc = 0.f;
    for (int a = 0; a < 8; a++) {
        const int i = atom0 + a;
        float accv = 0.f;
        #pragma unroll
        for (int j = 0; j < 12; j++) {
            float m = mask[i * 12 + j];
            if (m != 0.f) {
                const float* gp = g_gated + (size_t)(i * 12 + j) * 256;
                float hf = (gp[c]       - mf) * sf + bf;
                float hc = (gp[c + 128] - mc) * sc + bcr;
                accv += sigmoid_fast(hf) * softplus_fast(hc);
            }
        }
        g_nbrsum[(size_t)i * 128 + c] = accv;
        sloc  += accv;
        ssloc  = fmaf(accv, accv, ssloc);
    }
    atomicAdd(&g_stats2[c],       sloc);
    atomicAdd(&g_stats2[128 + c], ssloc);
}

// ---------------- kernel F: out = softplus(atom + BN2(nbrsum)) ----------------
__global__ void __launch_bounds__(256) kernelF(
    const float* __restrict__ atom,
    const float* __restrict__ gamma2, const float* __restrict__ beta2,
    float* __restrict__ out)
{
    int t = blockIdx.x * 256 + threadIdx.x;
    if (t >= N_ATOMS * 128) return;
    int c = t & 127;
    const float invN = 1.f / (float)N_ATOMS;
    float mean = g_stats2[c] * invN;
    float var  = g_stats2[128 + c] * invN - mean * mean;
    float x = (g_nbrsum[t] - mean) * rsqrtf(var + BN_EPS) * gamma2[c] + beta2[c];
    out[t] = softplus_fast(atom[t] + x);
}

// ---------------- launch ----------------
extern "C" void kernel_launch(void* const* d_in, const int* in_sizes, int n_in,
                              void* d_out, int out_size)
{
    const float* atom   = (const float*)d_in[0];
    const float* nbr    = (const float*)d_in[1];
    const int*   idx    = (const int*)  d_in[2];
    const float* mask   = (const float*)d_in[3];
    const float* W      = (const float*)d_in[4];
    const float* bias   = (const float*)d_in[5];
    const float* gamma1 = (const float*)d_in[6];
    const float* beta1  = (const float*)d_in[7];
    const float* gamma2 = (const float*)d_in[8];
    const float* beta2  = (const float*)d_in[9];
    float* out = (float*)d_out;

    zero_stats_kernel<<<1, 1024>>>();
    prepack_kernel<<<64, 256>>>(W);
    compact_kernel<<<(N_ROWS + 255) / 256, 256>>>(mask);
    gemmA_kernel<<<dim3((N_ATOMS + 31) / 32, 2), 256>>>(atom, W, bias);
    kernelB<<<(N_ROWS + 31) / 32, 256>>>(nbr, idx);
    kernelD<<<N_ATOMS / 8, 128>>>(mask, gamma1, beta1);
    kernelF<<<(N_ATOMS * 128) / 256, 256>>>(atom, gamma2, beta2, out);
}

// round 6
// speedup vs baseline: 1.3643x; 1.3643x over previous
#include <cuda_runtime.h>
#include <cstdint>

#define N_ATOMS 50000
#define M_NBR   12
#define N_ROWS  (N_ATOMS * M_NBR)
#define BN_EPS  1e-5f

// Round 6 = Round 5 resubmit (R5 bench died to container infra failure, no signal).

// ---------------- scratch (device globals; no allocation) ----------------
__device__ float  g_P[(size_t)N_ATOMS * 512];       // [i][0:256)=atom@W1+bias, [256:512)=atom@W2
__device__ float  g_gated[(size_t)N_ROWS * 256];    // pre-BN gated features (active rows only)
__device__ float  g_nbrsum[(size_t)N_ATOMS * 128];
__device__ float  g_stats1[513];                    // S[256], SS[256], cnt
__device__ float  g_stats2[256];                    // S2[128], SS2[128]
__device__ int    g_rows[N_ROWS];                   // compacted active row indices
__device__ int    g_nactive;

// ---------------- f32x2 helpers ----------------
__device__ __forceinline__ uint64_t dup2(float x) {
    uint64_t r; asm("mov.b64 %0, {%1, %1};" : "=l"(r) : "f"(x)); return r;
}
__device__ __forceinline__ void fma2(uint64_t& d, uint64_t a, uint64_t b) {
    asm("fma.rn.f32x2 %0, %1, %2, %0;" : "+l"(d) : "l"(a), "l"(b));
}
__device__ __forceinline__ float lo32(uint64_t v) { return __uint_as_float((unsigned)(v & 0xffffffffu)); }
__device__ __forceinline__ float hi32(uint64_t v) { return __uint_as_float((unsigned)(v >> 32)); }

__device__ __forceinline__ float sigmoid_fast(float x) {
    float z = __expf(-fabsf(x));
    return __fdividef((x >= 0.f) ? 1.f : z, 1.f + z);
}
__device__ __forceinline__ float softplus_fast(float x) {
    return fmaxf(x, 0.f) + __logf(1.f + __expf(-fabsf(x)));
}

// ---------------- kernel 0: zero stats ----------------
__global__ void zero_stats_kernel() {
    int t = threadIdx.x;
    if (t < 513) g_stats1[t] = 0.f;
    if (t < 256) g_stats2[t] = 0.f;
    if (t == 0)  g_nactive = 0;
}

// ---------------- kernel C: compact active rows ----------------
__global__ void compact_kernel(const float* __restrict__ mask) {
    int t = blockIdx.x * 256 + threadIdx.x;
    bool in = (t < N_ROWS) && (mask[t] != 0.f);
    unsigned b = __ballot_sync(0xffffffffu, in);
    int lane = threadIdx.x & 31;
    int cnt = __popc(b);
    int base = 0;
    if (lane == 0 && cnt) {
        base = atomicAdd(&g_nactive, cnt);
        atomicAdd(&g_stats1[512], (float)cnt);
    }
    base = __shfl_sync(0xffffffffu, base, 0);
    if (in) g_rows[base + __popc(b & ((1u << lane) - 1u))] = t;
}

// ---------------- kernel A: P = atom @ [W1|W2] + bias-fold ----
// Grid (782, 2): 64 rows x 256 cols per block; blockIdx.y selects W1/W2 half.
// Thread: rows rg*8..rg*8+7, col-pairs (2cx+64q, 2cx+64q+1), q=0..3.
// Inner k: 2 broadcast LDS.128 (A) + 8 reg-dups + 4 LDS.64 (plain W pairs) + 32 fma2.
__global__ void __launch_bounds__(256, 2) gemmA_kernel(
    const float* __restrict__ atom, const float* __restrict__ W,
    const float* __restrict__ bias)
{
    __shared__ float s_a[32 * 64];     // chunk [kk][r], 8KB
    __shared__ float s_w[32 * 256];    // chunk [kk][c] plain, 32KB

    const int tid  = threadIdx.x;
    const int row0 = blockIdx.x * 64;
    const int h    = blockIdx.y;       // 0 -> W1 (P cols 0..255), 1 -> W2 (P cols 256..511)

    const int rg = tid >> 5;           // warp id: rows rg*8 .. rg*8+7
    const int cx = tid & 31;           // col-pairs at 2cx + 64q

    uint64_t acc[8][4];
    #pragma unroll
    for (int r = 0; r < 8; r++)
        #pragma unroll
        for (int q = 0; q < 4; q++) acc[r][q] = 0ull;

    for (int chunk = 0; chunk < 4; chunk++) {
        const int k0 = chunk * 32;
        __syncthreads();
        // stage A chunk: 64 rows x 32 k (transposed)
        for (int t = tid; t < 512; t += 256) {
            int r  = t & 63;
            int kq = t >> 6;                       // 0..7 -> k-quad
            float4 v = make_float4(0.f, 0.f, 0.f, 0.f);
            int gr = row0 + r;
            if (gr < N_ATOMS) v = *(const float4*)(atom + (size_t)gr * 128 + k0 + kq * 4);
            s_a[(kq * 4 + 0) * 64 + r] = v.x;
            s_a[(kq * 4 + 1) * 64 + r] = v.y;
            s_a[(kq * 4 + 2) * 64 + r] = v.z;
            s_a[(kq * 4 + 3) * 64 + r] = v.w;
        }
        // stage W chunk: 32 k x 256 c (plain floats)
        for (int t = tid; t < 2048; t += 256) {
            int kk = t >> 6;
            int c4 = (t & 63) * 4;
            *(float4*)(s_w + kk * 256 + c4) =
                *(const float4*)(W + (size_t)(h * 128 + k0 + kk) * 256 + c4);
        }
        __syncthreads();

        #pragma unroll 4
        for (int kk = 0; kk < 32; kk++) {
            const float* sa = s_a + kk * 64 + rg * 8;
            float4 a03 = *(const float4*)(sa);         // broadcast
            float4 a47 = *(const float4*)(sa + 4);
            uint64_t ad[8] = { dup2(a03.x), dup2(a03.y), dup2(a03.z), dup2(a03.w),
                               dup2(a47.x), dup2(a47.y), dup2(a47.z), dup2(a47.w) };
            const uint64_t* sw = (const uint64_t*)(s_w + kk * 256) + cx;
            uint64_t wp[4];
            #pragma unroll
            for (int q = 0; q < 4; q++) wp[q] = sw[32 * q];
            #pragma unroll
            for (int r = 0; r < 8; r++)
                #pragma unroll
                for (int q = 0; q < 4; q++)
                    fma2(acc[r][q], ad[r], wp[q]);
        }
    }

    // epilogue: float2 stores; fold bias into h==0 half
    float2 bb[4];
    #pragma unroll
    for (int q = 0; q < 4; q++)
        bb[q] = (h == 0) ? *(const float2*)(bias + 2 * cx + 64 * q) : make_float2(0.f, 0.f);

    #pragma unroll
    for (int r = 0; r < 8; r++) {
        int row = row0 + rg * 8 + r;
        if (row >= N_ATOMS) break;
        float2* dst = (float2*)(g_P + (size_t)row * 512 + h * 256) + cx;
        #pragma unroll
        for (int q = 0; q < 4; q++) {
            float2 v = make_float2(lo32(acc[r][q]) + bb[q].x, hi32(acc[r][q]) + bb[q].y);
            dst[32 * q] = v;
        }
    }
}

// ---------------- kernel B: gated = nbr@W3 + P1(+b) + P2[idx] (active rows) ----
// 64 compacted rows x 256 cols per block; same microkernel shape as gemmA.
__global__ void __launch_bounds__(256, 2) kernelB(
    const float* __restrict__ nbr, const int* __restrict__ idx,
    const float* __restrict__ W)
{
    __shared__ float s_v[64 * 64];     // [k][r], 16KB
    __shared__ float s_w[16 * 256];    // W3 chunk plain, 16KB
    __shared__ int   s_row[64];
    __shared__ int   s_atom[64];
    __shared__ int   s_idx[64];
    __shared__ float s_st[512];        // per-col partial stats

    const int na    = g_nactive;
    const int slot0 = blockIdx.x * 64;
    if (slot0 >= na) return;

    const int tid = threadIdx.x;

    if (tid < 64) {
        int slot = slot0 + tid;
        int gr = (slot < na) ? g_rows[slot] : -1;
        s_row[tid]  = gr;
        s_atom[tid] = (gr >= 0) ? (gr / 12) : 0;
        s_idx[tid]  = (gr >= 0) ? idx[gr] : 0;
    }
    s_st[tid] = 0.f;
    s_st[tid + 256] = 0.f;
    __syncthreads();

    // stage V: 64 rows x 64 k (transposed)
    for (int t = tid; t < 1024; t += 256) {
        int r  = t & 63;
        int kq = t >> 6;                 // 0..15
        int gr = s_row[r];
        float4 v = make_float4(0.f, 0.f, 0.f, 0.f);
        if (gr >= 0) v = *(const float4*)(nbr + (size_t)gr * 64 + kq * 4);
        s_v[(kq * 4 + 0) * 64 + r] = v.x;
        s_v[(kq * 4 + 1) * 64 + r] = v.y;
        s_v[(kq * 4 + 2) * 64 + r] = v.z;
        s_v[(kq * 4 + 3) * 64 + r] = v.w;
    }

    const int rg = tid >> 5;
    const int cx = tid & 31;

    uint64_t acc[8][4];
    #pragma unroll
    for (int r = 0; r < 8; r++)
        #pragma unroll
        for (int q = 0; q < 4; q++) acc[r][q] = 0ull;

    for (int chunk = 0; chunk < 4; chunk++) {
        const int k0 = chunk * 16;
        __syncthreads();
        for (int t = tid; t < 1024; t += 256) {      // 16 k x 256 c
            int kk = t >> 6;
            int c4 = (t & 63) * 4;
            *(float4*)(s_w + kk * 256 + c4) =
                *(const float4*)(W + (size_t)(256 + k0 + kk) * 256 + c4);
        }
        __syncthreads();

        #pragma unroll 4
        for (int kk = 0; kk < 16; kk++) {
            const float* sv = s_v + (k0 + kk) * 64 + rg * 8;
            float4 a03 = *(const float4*)(sv);
            float4 a47 = *(const float4*)(sv + 4);
            uint64_t ad[8] = { dup2(a03.x), dup2(a03.y), dup2(a03.z), dup2(a03.w),
                               dup2(a47.x), dup2(a47.y), dup2(a47.z), dup2(a47.w) };
            const uint64_t* sw = (const uint64_t*)(s_w + kk * 256) + cx;
            uint64_t wp[4];
            #pragma unroll
            for (int q = 0; q < 4; q++) wp[q] = sw[32 * q];
            #pragma unroll
            for (int r = 0; r < 8; r++)
                #pragma unroll
                for (int q = 0; q < 4; q++)
                    fma2(acc[r][q], ad[r], wp[q]);
        }
    }

    // epilogue: add P1(+bias) + P2[idx], store gated as float2, per-col stats
    float2 sq[4], ssq[4];
    #pragma unroll
    for (int q = 0; q < 4; q++) { sq[q] = make_float2(0.f, 0.f); ssq[q] = make_float2(0.f, 0.f); }

    #pragma unroll
    for (int r = 0; r < 8; r++) {
        int rr   = rg * 8 + r;
        int slot = slot0 + rr;
        if (slot >= na) break;
        int gr = s_row[rr];
        const float2* P1 = (const float2*)(g_P + (size_t)s_atom[rr] * 512) + cx;
        const float2* P2 = (const float2*)(g_P + (size_t)s_idx[rr] * 512 + 256) + cx;
        float2* Gout = (float2*)(g_gated + (size_t)gr * 256) + cx;
        #pragma unroll
        for (int q = 0; q < 4; q++) {
            float2 p1 = P1[32 * q];
            float2 p2 = P2[32 * q];
            float gx = lo32(acc[r][q]) + p1.x + p2.x;
            float gy = hi32(acc[r][q]) + p1.y + p2.y;
            Gout[32 * q] = make_float2(gx, gy);
            sq[q].x += gx;  sq[q].y += gy;
            ssq[q].x = fmaf(gx, gx, ssq[q].x);
            ssq[q].y = fmaf(gy, gy, ssq[q].y);
        }
    }
    #pragma unroll
    for (int q = 0; q < 4; q++) {
        int c = 2 * cx + 64 * q;
        atomicAdd(&s_st[c],           sq[q].x);
        atomicAdd(&s_st[c + 1],       sq[q].y);
        atomicAdd(&s_st[256 + c],     ssq[q].x);
        atomicAdd(&s_st[256 + c + 1], ssq[q].y);
    }
    __syncthreads();
    atomicAdd(&g_stats1[tid],       s_st[tid]);
    atomicAdd(&g_stats1[256 + tid], s_st[256 + tid]);
}

// ---------------- kernel D: BN1 + sigmoid*softplus + sum_j, + BN2 stats ----
__global__ void __launch_bounds__(128) kernelD(
    const float* __restrict__ mask,
    const float* __restrict__ gamma1, const float* __restrict__ beta1)
{
    const int c     = threadIdx.x;
    const int atom0 = blockIdx.x * 8;

    const float inv_cnt = __fdividef(1.f, g_stats1[512]);
    const float mf = g_stats1[c]       * inv_cnt;
    const float mc = g_stats1[c + 128] * inv_cnt;
    const float vf = g_stats1[256 + c]       * inv_cnt - mf * mf;
    const float vc = g_stats1[256 + c + 128] * inv_cnt - mc * mc;
    const float sf = rsqrtf(vf + BN_EPS) * gamma1[c];
    const float sc = rsqrtf(vc + BN_EPS) * gamma1[c + 128];
    const float bf = beta1[c];
    const float bcr = beta1[c + 128];

    float sloc = 0.f, ssloc = 0.f;
    for (int a = 0; a < 8; a++) {
        const int i = atom0 + a;
        float accv = 0.f;
        #pragma unroll
        for (int j = 0; j < 12; j++) {
            float m = mask[i * 12 + j];
            if (m != 0.f) {
                const float* gp = g_gated + (size_t)(i * 12 + j) * 256;
                float hf = (gp[c]       - mf) * sf + bf;
                float hc = (gp[c + 128] - mc) * sc + bcr;
                accv += sigmoid_fast(hf) * softplus_fast(hc);
            }
        }
        g_nbrsum[(size_t)i * 128 + c] = accv;
        sloc  += accv;
        ssloc  = fmaf(accv, accv, ssloc);
    }
    atomicAdd(&g_stats2[c],       sloc);
    atomicAdd(&g_stats2[128 + c], ssloc);
}

// ---------------- kernel F: out = softplus(atom + BN2(nbrsum)) ----------------
__global__ void __launch_bounds__(256) kernelF(
    const float* __restrict__ atom,
    const float* __restrict__ gamma2, const float* __restrict__ beta2,
    float* __restrict__ out)
{
    int t = blockIdx.x * 256 + threadIdx.x;
    if (t >= N_ATOMS * 128) return;
    int c = t & 127;
    const float invN = 1.f / (float)N_ATOMS;
    float mean = g_stats2[c] * invN;
    float var  = g_stats2[128 + c] * invN - mean * mean;
    float x = (g_nbrsum[t] - mean) * rsqrtf(var + BN_EPS) * gamma2[c] + beta2[c];
    out[t] = softplus_fast(atom[t] + x);
}

// ---------------- launch ----------------
extern "C" void kernel_launch(void* const* d_in, const int* in_sizes, int n_in,
                              void* d_out, int out_size)
{
    const float* atom   = (const float*)d_in[0];
    const float* nbr    = (const float*)d_in[1];
    const int*   idx    = (const int*)  d_in[2];
    const float* mask   = (const float*)d_in[3];
    const float* W      = (const float*)d_in[4];
    const float* bias   = (const float*)d_in[5];
    const float* gamma1 = (const float*)d_in[6];
    const float* beta1  = (const float*)d_in[7];
    const float* gamma2 = (const float*)d_in[8];
    const float* beta2  = (const float*)d_in[9];
    float* out = (float*)d_out;

    zero_stats_kernel<<<1, 1024>>>();
    compact_kernel<<<(N_ROWS + 255) / 256, 256>>>(mask);
    gemmA_kernel<<<dim3((N_ATOMS + 63) / 64, 2), 256>>>(atom, W, bias);
    kernelB<<<(N_ROWS + 63) / 64, 256>>>(nbr, idx, W);
    kernelD<<<N_ATOMS / 8, 128>>>(mask, gamma1, beta1);
    kernelF<<<(N_ATOMS * 128) / 256, 256>>>(atom, gamma2, beta2, out);
}

// round 7
// speedup vs baseline: 1.7428x; 1.2775x over previous
#include <cuda_runtime.h>
#include <cstdint>

#define N_ATOMS 50000
#define M_NBR   12
#define N_ROWS  (N_ATOMS * M_NBR)
#define BN_EPS  1e-5f

// ---------------- scratch (device globals; no allocation) ----------------
__device__ float  g_P[(size_t)N_ATOMS * 512];       // [i][0:256)=atom@W1+bias, [256:512)=atom@W2
__device__ float  g_gated[(size_t)N_ROWS * 256];    // pre-BN gated features (active rows only)
__device__ float  g_nbrsum[(size_t)N_ATOMS * 128];
__device__ float  g_stats1[513];                    // S[256], SS[256], cnt
__device__ float  g_stats2[256];                    // S2[128], SS2[128]
__device__ int    g_rows[N_ROWS];                   // compacted active row indices
__device__ int    g_nactive;

#define SMEM_A_BYTES (65536)     // gemmA: s_a 32KB + s_w 32KB
#define SMEM_B_BYTES (84736)     // kernelB: s_v 16KB + s_w 64KB + meta 768B + s_st 2KB

// ---------------- f32x2 helpers ----------------
__device__ __forceinline__ uint64_t dup2(float x) {
    uint64_t r; asm("mov.b64 %0, {%1, %1};" : "=l"(r) : "f"(x)); return r;
}
__device__ __forceinline__ void fma2(uint64_t& d, uint64_t a, uint64_t b) {
    asm("fma.rn.f32x2 %0, %1, %2, %0;" : "+l"(d) : "l"(a), "l"(b));
}
__device__ __forceinline__ float lo32(uint64_t v) { return __uint_as_float((unsigned)(v & 0xffffffffu)); }
__device__ __forceinline__ float hi32(uint64_t v) { return __uint_as_float((unsigned)(v >> 32)); }

__device__ __forceinline__ float sigmoid_fast(float x) {
    float z = __expf(-fabsf(x));
    return __fdividef((x >= 0.f) ? 1.f : z, 1.f + z);
}
__device__ __forceinline__ float softplus_fast(float x) {
    return fmaxf(x, 0.f) + __logf(1.f + __expf(-fabsf(x)));
}

// ---------------- kernel 0: zero stats ----------------
__global__ void zero_stats_kernel() {
    int t = threadIdx.x;
    if (t < 513) g_stats1[t] = 0.f;
    if (t < 256) g_stats2[t] = 0.f;
    if (t == 0)  g_nactive = 0;
}

// ---------------- kernel C: compact active rows ----------------
__global__ void compact_kernel(const float* __restrict__ mask) {
    int t = blockIdx.x * 256 + threadIdx.x;
    bool in = (t < N_ROWS) && (mask[t] != 0.f);
    unsigned b = __ballot_sync(0xffffffffu, in);
    int lane = threadIdx.x & 31;
    int cnt = __popc(b);
    int base = 0;
    if (lane == 0 && cnt) {
        base = atomicAdd(&g_nactive, cnt);
        atomicAdd(&g_stats1[512], (float)cnt);
    }
    base = __shfl_sync(0xffffffffu, base, 0);
    if (in) g_rows[base + __popc(b & ((1u << lane) - 1u))] = t;
}

// ---------------- kernel A: P = atom @ [W1|W2] + bias-fold ----
// Grid (782, 2): 64 rows x 256 cols per block; blockIdx.y selects W1/W2.
// Thread: rows rg*8..rg*8+7, col-quads 4cx+128q (q=0..1).
// A tile staged once (full K); W staged in 32-k chunks.
__global__ void __launch_bounds__(256, 2) gemmA_kernel(
    const float* __restrict__ atom, const float* __restrict__ W,
    const float* __restrict__ bias)
{
    extern __shared__ float smem[];
    float* s_a = smem;                 // [k][r] 128x64
    float* s_w = smem + 128 * 64;      // [kk][c] 32x256

    const int tid  = threadIdx.x;
    const int row0 = blockIdx.x * 64;
    const int h    = blockIdx.y;

    const int rg = tid >> 5;           // rows rg*8 .. rg*8+7
    const int cx = tid & 31;           // col quads at 4cx + 128q

    // stage full A tile: 64 rows x 128 k, transposed
    for (int t = tid; t < 2048; t += 256) {
        int r  = t & 63;
        int kq = t >> 6;                           // 0..31
        float4 v = make_float4(0.f, 0.f, 0.f, 0.f);
        int gr = row0 + r;
        if (gr < N_ATOMS) v = *(const float4*)(atom + (size_t)gr * 128 + kq * 4);
        s_a[(kq * 4 + 0) * 64 + r] = v.x;
        s_a[(kq * 4 + 1) * 64 + r] = v.y;
        s_a[(kq * 4 + 2) * 64 + r] = v.z;
        s_a[(kq * 4 + 3) * 64 + r] = v.w;
    }

    uint64_t acc[8][4];
    #pragma unroll
    for (int r = 0; r < 8; r++)
        #pragma unroll
        for (int j = 0; j < 4; j++) acc[r][j] = 0ull;

    for (int chunk = 0; chunk < 4; chunk++) {
        const int k0 = chunk * 32;
        __syncthreads();
        for (int t = tid; t < 2048; t += 256) {    // 32 k x 256 c
            int kk = t >> 6;
            int c4 = (t & 63) * 4;
            *(float4*)(s_w + kk * 256 + c4) =
                *(const float4*)(W + (size_t)(h * 128 + k0 + kk) * 256 + c4);
        }
        __syncthreads();

        #pragma unroll 4
        for (int kk = 0; kk < 32; kk++) {
            const float* sa = s_a + (k0 + kk) * 64 + rg * 8;
            float4 a03 = *(const float4*)(sa);
            float4 a47 = *(const float4*)(sa + 4);
            uint64_t ad[8] = { dup2(a03.x), dup2(a03.y), dup2(a03.z), dup2(a03.w),
                               dup2(a47.x), dup2(a47.y), dup2(a47.z), dup2(a47.w) };
            ulonglong2 w01 = *(const ulonglong2*)(s_w + kk * 256 + 4 * cx);
            ulonglong2 w23 = *(const ulonglong2*)(s_w + kk * 256 + 4 * cx + 128);
            uint64_t wp[4] = { w01.x, w01.y, w23.x, w23.y };
            #pragma unroll
            for (int r = 0; r < 8; r++)
                #pragma unroll
                for (int j = 0; j < 4; j++)
                    fma2(acc[r][j], ad[r], wp[j]);
        }
    }

    // epilogue: float4 stores, bias folded into h==0 half
    float4 ba = make_float4(0.f, 0.f, 0.f, 0.f), bb = ba;
    if (h == 0) {
        ba = *(const float4*)(bias + 4 * cx);
        bb = *(const float4*)(bias + 4 * cx + 128);
    }

    #pragma unroll
    for (int r = 0; r < 8; r++) {
        int row = row0 + rg * 8 + r;
        if (row >= N_ATOMS) break;
        float* dst = g_P + (size_t)row * 512 + h * 256;
        float4 va = make_float4(lo32(acc[r][0]) + ba.x, hi32(acc[r][0]) + ba.y,
                                lo32(acc[r][1]) + ba.z, hi32(acc[r][1]) + ba.w);
        float4 vb = make_float4(lo32(acc[r][2]) + bb.x, hi32(acc[r][2]) + bb.y,
                                lo32(acc[r][3]) + bb.z, hi32(acc[r][3]) + bb.w);
        *(float4*)(dst + 4 * cx)       = va;
        *(float4*)(dst + 4 * cx + 128) = vb;
    }
}

// ---------------- kernel B: gated = nbr@W3 + P1(+b) + P2[idx] (active rows) ----
// 64 compacted rows x 256 cols per block; W3 staged entirely once (64KB).
__global__ void __launch_bounds__(256, 2) kernelB(
    const float* __restrict__ nbr, const int* __restrict__ idx,
    const float* __restrict__ W)
{
    extern __shared__ float smem[];
    float* s_v   = smem;                        // [k][r] 64x64 (16KB)
    float* s_w   = smem + 64 * 64;              // [k][c] 64x256 (64KB)
    int*   s_row = (int*)(s_w + 64 * 256);      // 64
    int*   s_atom= s_row + 64;
    int*   s_idx = s_atom + 64;
    float* s_st  = (float*)(s_idx + 64);        // 512

    const int na    = g_nactive;
    const int slot0 = blockIdx.x * 64;
    if (slot0 >= na) return;

    const int tid = threadIdx.x;

    if (tid < 64) {
        int slot = slot0 + tid;
        int gr = (slot < na) ? g_rows[slot] : -1;
        s_row[tid]  = gr;
        s_atom[tid] = (gr >= 0) ? (gr / 12) : 0;
        s_idx[tid]  = (gr >= 0) ? idx[gr] : 0;
    }
    s_st[tid] = 0.f;
    s_st[tid + 256] = 0.f;
    __syncthreads();

    // stage V: 64 rows x 64 k (transposed)
    for (int t = tid; t < 1024; t += 256) {
        int r  = t & 63;
        int kq = t >> 6;                 // 0..15
        int gr = s_row[r];
        float4 v = make_float4(0.f, 0.f, 0.f, 0.f);
        if (gr >= 0) v = *(const float4*)(nbr + (size_t)gr * 64 + kq * 4);
        s_v[(kq * 4 + 0) * 64 + r] = v.x;
        s_v[(kq * 4 + 1) * 64 + r] = v.y;
        s_v[(kq * 4 + 2) * 64 + r] = v.z;
        s_v[(kq * 4 + 3) * 64 + r] = v.w;
    }
    // stage full W3: 64 k x 256 c
    for (int t = tid; t < 4096; t += 256) {
        int k  = t >> 6;
        int c4 = (t & 63) * 4;
        *(float4*)(s_w + k * 256 + c4) =
            *(const float4*)(W + (size_t)(256 + k) * 256 + c4);
    }
    __syncthreads();

    const int rg = tid >> 5;
    const int cx = tid & 31;             // col quads at 4cx + 128q

    uint64_t acc[8][4];
    #pragma unroll
    for (int r = 0; r < 8; r++)
        #pragma unroll
        for (int j = 0; j < 4; j++) acc[r][j] = 0ull;

    #pragma unroll 4
    for (int k = 0; k < 64; k++) {
        const float* sv = s_v + k * 64 + rg * 8;
        float4 a03 = *(const float4*)(sv);
        float4 a47 = *(const float4*)(sv + 4);
        uint64_t ad[8] = { dup2(a03.x), dup2(a03.y), dup2(a03.z), dup2(a03.w),
                           dup2(a47.x), dup2(a47.y), dup2(a47.z), dup2(a47.w) };
        ulonglong2 w01 = *(const ulonglong2*)(s_w + k * 256 + 4 * cx);
        ulonglong2 w23 = *(const ulonglong2*)(s_w + k * 256 + 4 * cx + 128);
        uint64_t wp[4] = { w01.x, w01.y, w23.x, w23.y };
        #pragma unroll
        for (int r = 0; r < 8; r++)
            #pragma unroll
            for (int j = 0; j < 4; j++)
                fma2(acc[r][j], ad[r], wp[j]);
    }

    // epilogue: add P1(+bias) + P2[idx], float4 stores, per-col stats
    float sqa[4] = {0,0,0,0}, sqb[4] = {0,0,0,0};
    float ssa[4] = {0,0,0,0}, ssb[4] = {0,0,0,0};

    #pragma unroll
    for (int r = 0; r < 8; r++) {
        int rr   = rg * 8 + r;
        int slot = slot0 + rr;
        if (slot >= na) break;
        int gr = s_row[rr];
        const float* P1 = g_P + (size_t)s_atom[rr] * 512;
        const float* P2 = g_P + (size_t)s_idx[rr] * 512 + 256;
        float4 p1a = *(const float4*)(P1 + 4 * cx);
        float4 p1b = *(const float4*)(P1 + 4 * cx + 128);
        float4 p2a = *(const float4*)(P2 + 4 * cx);
        float4 p2b = *(const float4*)(P2 + 4 * cx + 128);
        float4 va = make_float4(lo32(acc[r][0]) + p1a.x + p2a.x,
                                hi32(acc[r][0]) + p1a.y + p2a.y,
                                lo32(acc[r][1]) + p1a.z + p2a.z,
                                hi32(acc[r][1]) + p1a.w + p2a.w);
        float4 vb = make_float4(lo32(acc[r][2]) + p1b.x + p2b.x,
                                hi32(acc[r][2]) + p1b.y + p2b.y,
                                lo32(acc[r][3]) + p1b.z + p2b.z,
                                hi32(acc[r][3]) + p1b.w + p2b.w);
        float* Gout = g_gated + (size_t)gr * 256;
        *(float4*)(Gout + 4 * cx)       = va;
        *(float4*)(Gout + 4 * cx + 128) = vb;
        sqa[0] += va.x; sqa[1] += va.y; sqa[2] += va.z; sqa[3] += va.w;
        sqb[0] += vb.x; sqb[1] += vb.y; sqb[2] += vb.z; sqb[3] += vb.w;
        ssa[0] = fmaf(va.x, va.x, ssa[0]); ssa[1] = fmaf(va.y, va.y, ssa[1]);
        ssa[2] = fmaf(va.z, va.z, ssa[2]); ssa[3] = fmaf(va.w, va.w, ssa[3]);
        ssb[0] = fmaf(vb.x, vb.x, ssb[0]); ssb[1] = fmaf(vb.y, vb.y, ssb[1]);
        ssb[2] = fmaf(vb.z, vb.z, ssb[2]); ssb[3] = fmaf(vb.w, vb.w, ssb[3]);
    }
    #pragma unroll
    for (int t = 0; t < 4; t++) {
        atomicAdd(&s_st[4 * cx + t],             sqa[t]);
        atomicAdd(&s_st[4 * cx + 128 + t],       sqb[t]);
        atomicAdd(&s_st[256 + 4 * cx + t],       ssa[t]);
        atomicAdd(&s_st[256 + 4 * cx + 128 + t], ssb[t]);
    }
    __syncthreads();
    atomicAdd(&g_stats1[tid],       s_st[tid]);
    atomicAdd(&g_stats1[256 + tid], s_st[256 + tid]);
}

// ---------------- kernel D: BN1 + sigmoid*softplus + sum_j, + BN2 stats ----
// 16 atoms per block, 256 threads: lane=channel pair (float2), grp=atom group.
__global__ void __launch_bounds__(256) kernelD(
    const float* __restrict__ mask,
    const float* __restrict__ gamma1, const float* __restrict__ beta1)
{
    __shared__ float s2[256];

    const int tid   = threadIdx.x;
    const int lane  = tid & 63;          // channel pair c = 2*lane (0..126)
    const int grp   = tid >> 6;          // 0..3
    const int atom0 = blockIdx.x * 16;

    s2[tid] = 0.f;

    const int c = 2 * lane;
    const float inv_cnt = __fdividef(1.f, g_stats1[512]);
    float2 Sf  = *(const float2*)(g_stats1 + c);
    float2 Sc  = *(const float2*)(g_stats1 + 128 + c);
    float2 SSf = *(const float2*)(g_stats1 + 256 + c);
    float2 SSc = *(const float2*)(g_stats1 + 256 + 128 + c);
    float2 gf  = *(const float2*)(gamma1 + c);
    float2 gc  = *(const float2*)(gamma1 + 128 + c);
    float2 bf  = *(const float2*)(beta1 + c);
    float2 bcr = *(const float2*)(beta1 + 128 + c);

    float2 mf = make_float2(Sf.x * inv_cnt, Sf.y * inv_cnt);
    float2 mc = make_float2(Sc.x * inv_cnt, Sc.y * inv_cnt);
    float2 sf = make_float2(rsqrtf(SSf.x * inv_cnt - mf.x * mf.x + BN_EPS) * gf.x,
                            rsqrtf(SSf.y * inv_cnt - mf.y * mf.y + BN_EPS) * gf.y);
    float2 sc = make_float2(rsqrtf(SSc.x * inv_cnt - mc.x * mc.x + BN_EPS) * gc.x,
                            rsqrtf(SSc.y * inv_cnt - mc.y * mc.y + BN_EPS) * gc.y);
    __syncthreads();

    float2 sloc = make_float2(0.f, 0.f), ssloc = make_float2(0.f, 0.f);

    #pragma unroll
    for (int a = 0; a < 4; a++) {
        const int i = atom0 + grp * 4 + a;
        float m[12];
        #pragma unroll
        for (int j = 0; j < 12; j++) m[j] = __ldg(mask + i * 12 + j);

        float2 accv = make_float2(0.f, 0.f);
        #pragma unroll
        for (int half = 0; half < 2; half++) {
            float2 vf[6], vc[6];
            #pragma unroll
            for (int j = 0; j < 6; j++) {
                int jj = half * 6 + j;
                const float* gp = g_gated + (size_t)(i * 12 + jj) * 256;
                bool act = (m[jj] != 0.f);
                vf[j] = act ? *(const float2*)(gp + c)       : make_float2(0.f, 0.f);
                vc[j] = act ? *(const float2*)(gp + 128 + c) : make_float2(0.f, 0.f);
            }
            #pragma unroll
            for (int j = 0; j < 6; j++) {
                int jj = half * 6 + j;
                if (m[jj] != 0.f) {
                    float hfx = (vf[j].x - mf.x) * sf.x + bf.x;
                    float hfy = (vf[j].y - mf.y) * sf.y + bf.y;
                    float hcx = (vc[j].x - mc.x) * sc.x + bcr.x;
                    float hcy = (vc[j].y - mc.y) * sc.y + bcr.y;
                    accv.x += sigmoid_fast(hfx) * softplus_fast(hcx);
                    accv.y += sigmoid_fast(hfy) * softplus_fast(hcy);
                }
            }
        }
        *(float2*)(g_nbrsum + (size_t)i * 128 + c) = accv;
        sloc.x  += accv.x;               sloc.y  += accv.y;
        ssloc.x  = fmaf(accv.x, accv.x, ssloc.x);
        ssloc.y  = fmaf(accv.y, accv.y, ssloc.y);
    }
    atomicAdd(&s2[c],           sloc.x);
    atomicAdd(&s2[c + 1],       sloc.y);
    atomicAdd(&s2[128 + c],     ssloc.x);
    atomicAdd(&s2[128 + c + 1], ssloc.y);
    __syncthreads();
    atomicAdd(&g_stats2[tid], s2[tid]);
}

// ---------------- kernel F: out = softplus(atom + BN2(nbrsum)) ----------------
__global__ void __launch_bounds__(256) kernelF(
    const float* __restrict__ atom,
    const float* __restrict__ gamma2, const float* __restrict__ beta2,
    float* __restrict__ out)
{
    int t = blockIdx.x * 256 + threadIdx.x;
    if (t >= N_ATOMS * 128) return;
    int c = t & 127;
    const float invN = 1.f / (float)N_ATOMS;
    float mean = g_stats2[c] * invN;
    float var  = g_stats2[128 + c] * invN - mean * mean;
    float x = (g_nbrsum[t] - mean) * rsqrtf(var + BN_EPS) * gamma2[c] + beta2[c];
    out[t] = softplus_fast(atom[t] + x);
}

// ---------------- launch ----------------
extern "C" void kernel_launch(void* const* d_in, const int* in_sizes, int n_in,
                              void* d_out, int out_size)
{
    const float* atom   = (const float*)d_in[0];
    const float* nbr    = (const float*)d_in[1];
    const int*   idx    = (const int*)  d_in[2];
    const float* mask   = (const float*)d_in[3];
    const float* W      = (const float*)d_in[4];
    const float* bias   = (const float*)d_in[5];
    const float* gamma1 = (const float*)d_in[6];
    const float* beta1  = (const float*)d_in[7];
    const float* gamma2 = (const float*)d_in[8];
    const float* beta2  = (const float*)d_in[9];
    float* out = (float*)d_out;

    cudaFuncSetAttribute(gemmA_kernel, cudaFuncAttributeMaxDynamicSharedMemorySize, SMEM_A_BYTES);
    cudaFuncSetAttribute(kernelB,      cudaFuncAttributeMaxDynamicSharedMemorySize, SMEM_B_BYTES);

    zero_stats_kernel<<<1, 1024>>>();
    compact_kernel<<<(N_ROWS + 255) / 256, 256>>>(mask);
    gemmA_kernel<<<dim3((N_ATOMS + 63) / 64, 2), 256, SMEM_A_BYTES>>>(atom, W, bias);
    kernelB<<<(N_ROWS + 63) / 64, 256, SMEM_B_BYTES>>>(nbr, idx, W);
    kernelD<<<N_ATOMS / 16, 256>>>(mask, gamma1, beta1);
    kernelF<<<(N_ATOMS * 128) / 256, 256>>>(atom, gamma2, beta2, out);
}